// round 14
// baseline (speedup 1.0000x reference)
#include <cuda_runtime.h>
#include <math.h>

#define NB 16
#define NA 65472
#define NC 81
#define NG 50
#define POS_TH 0.5f
#define FULL 0xffffffffu
#define NBLK 256                  // k2a blocks per batch
#define POSBMW 2048               // padded bitmap words per batch (NA/32 = 2046)
#define REG_TOT (NB * NBLK * 256) // regular plist slots
#define K4B 512                   // k4-role blocks in stage B
#define BTOT (NB + K4B)

__device__ float g_mining[NB * NA];
__device__ unsigned long long g_part[NB * NG * NBLK];
__device__ unsigned g_posbm[NB * POSBMW];   // positive bitmap (regular | forced)
__device__ unsigned g_bm[NB * POSBMW];      // forced-anchor bitmap
__device__ unsigned g_plist[REG_TOT];       // segmented: 256 slots per k2a block
__device__ unsigned g_flist[NB * 64];       // forced entries
__device__ int    g_blkcnt[NB * NBLK];
__device__ int    g_fcnt[NB];
__device__ int    g_pos_cnt[NB];
__device__ double g_pos_ce;                 // zero-init; reset at end of stage B
__device__ double g_loc_sum;
__device__ double g_neg_sum[NB];
__device__ int    g_done;

__device__ __forceinline__ unsigned fmap(float v) {
    unsigned u = __float_as_uint(v);
    return (u & 0x80000000u) ? ~u : (u | 0x80000000u);
}
__device__ __forceinline__ float funmap(unsigned u) {
    unsigned b = (u & 0x80000000u) ? (u & 0x7FFFFFFFu) : ~u;
    return __uint_as_float(b);
}

// ================= Stage A: k2a role (x < NBLK) || k1 role (x >= NBLK) ======
__global__ void kA(const float* __restrict__ conf, const float* __restrict__ gts,
                   const int* __restrict__ counts, const float* __restrict__ anchors) {
    __shared__ float4 sbox[NG];
    __shared__ float  sarea[NG];
    __shared__ unsigned long long spart[8][NG];
    __shared__ int s_pcnt;
    int b = blockIdx.y;
    int tid = threadIdx.x;
    int lane = tid & 31;
    int wid = tid >> 5;

    if (blockIdx.x < NBLK) {
        // ---------------- k2a: matching ----------------
        int x = blockIdx.x;
        if (tid == 0) s_pcnt = 0;
        if (tid < NG) {
            const float* gp = gts + ((size_t)b * NG + tid) * 5;
            float4 bx = make_float4(gp[0], gp[1], gp[2], gp[3]);
            sbox[tid] = bx;
            sarea[tid] = (bx.z - bx.x) * (bx.w - bx.y);
        }
        __syncthreads();
        int count = counts[b];
        int a = x * 256 + tid;
        float4 v = make_float4(0.f, 0.f, 0.f, 0.f);
        if (a < NA) v = reinterpret_cast<const float4*>(anchors)[a];
        float areaA = (v.z - v.x) * (v.w - v.y);
        float bi = -1.f;
        int bidx = 0;
        for (int g = 0; g < count; ++g) {
            float4 bx = sbox[g];
            float wx = fminf(v.z, bx.z) - fmaxf(v.x, bx.x);
            float wy = fminf(v.w, bx.w) - fmaxf(v.y, bx.y);
            wx = fmaxf(wx, 0.f); wy = fmaxf(wy, 0.f);
            float inter = wx * wy;
            float iou = __fdividef(inter, areaA + sarea[g] - inter + 1e-10f);
            if (a >= NA) iou = 0.f;
            if (iou > bi) { bi = iou; bidx = g; }      // first max kept (strict >)
            unsigned iu = __float_as_uint(iou);        // iou >= 0: uint order = float order
            unsigned mu = __reduce_max_sync(FULL, iu);
            unsigned ball = __ballot_sync(FULL, iu == mu);
            if (lane == (__ffs(ball) - 1)) {           // lowest lane = smallest anchor
                spart[wid][g] = ((unsigned long long)mu << 32) | (unsigned)(~(unsigned)a);
            }
        }
        bool reg_pos = (a < NA) && (bi >= POS_TH);
        unsigned pball = __ballot_sync(FULL, reg_pos);
        if (lane == 0) g_posbm[b * POSBMW + x * 8 + wid] = pball;  // positive bitmap word
        if (pball) {
            int leader = __ffs(pball) - 1;
            int base = 0;
            if (lane == leader) base = atomicAdd(&s_pcnt, __popc(pball));
            base = __shfl_sync(FULL, base, leader);
            if (reg_pos) {
                int off = __popc(pball & ((1u << lane) - 1u));
                g_plist[((size_t)b * NBLK + x) * 256 + base + off] =
                    ((unsigned)b << 23) | ((unsigned)a << 6) | (unsigned)bidx;
            }
        }
        __syncthreads();
        if (tid == 0) g_blkcnt[b * NBLK + x] = s_pcnt;
        if (tid < count) {
            unsigned long long best = spart[0][tid];
            #pragma unroll
            for (int k = 1; k < 8; ++k) {
                unsigned long long vv = spart[k][tid];
                if (vv > best) best = vv;
            }
            g_part[((size_t)b * NG + tid) * NBLK + x] = best;
        }
    } else {
        // ---------------- k1: logsumexp -> mining (2 anchors per warp) -------
        int x2 = blockIdx.x - NBLK;
        int a0 = (x2 * 8 + wid) * 2;
        const float* p0 = conf + ((size_t)b * NA + a0) * NC;
        const float* p1 = p0 + NC;
        float a_x0 = p0[lane];
        float b_x0 = p1[lane];
        float a_x1 = p0[32 + lane];
        float b_x1 = p1[32 + lane];
        float sa = __expf(a_x0) + __expf(a_x1);
        float sb = __expf(b_x0) + __expf(b_x1);
        if (lane < NC - 64) {
            sa += __expf(p0[64 + lane]);
            sb += __expf(p1[64 + lane]);
        }
        #pragma unroll
        for (int off = 16; off; off >>= 1) {
            sa += __shfl_xor_sync(FULL, sa, off);
            sb += __shfl_xor_sync(FULL, sb, off);
        }
        if (lane == 0) {
            g_mining[(size_t)b * NA + a0]     = __logf(sa) - a_x0;   // lse - conf[...,0]
            g_mining[(size_t)b * NA + a0 + 1] = __logf(sb) - b_x0;
        }
    }
}

// ===== K2b3: reduce partials -> best anchor/g; dedup; bitmaps; pos counts ===
__global__ void kRS(const int* __restrict__ counts) {
    __shared__ int s_anch[NG];
    __shared__ int s_regsum[8];
    __shared__ int s_fnew, s_fcnt;
    int b = blockIdx.x;
    int tid = threadIdx.x;
    int lane = tid & 31;
    int wid = tid >> 5;                 // 16 warps (512 threads)
    // zero forced bitmap for this batch
    for (int i = tid; i < POSBMW; i += 512) g_bm[b * POSBMW + i] = 0u;
    if (tid == 0) { s_fnew = 0; s_fcnt = 0; }
    // sum regular-positive counts (256 values)
    int c = (tid < NBLK) ? g_blkcnt[b * NBLK + tid] : 0;
    #pragma unroll
    for (int off = 16; off; off >>= 1) c += __shfl_xor_sync(FULL, c, off);
    if (lane == 0 && wid < 8) s_regsum[wid] = c;
    // per-g argmax over NBLK block partials (warp per g)
    int count = counts[b];
    for (int g = wid; g < count; g += 16) {
        const unsigned long long* pp = g_part + ((size_t)b * NG + g) * NBLK;
        unsigned long long best = 0ull;
        #pragma unroll
        for (int k = 0; k < NBLK / 32; ++k) {
            unsigned long long vv = pp[lane + 32 * k];
            if (vv > best) best = vv;
        }
        #pragma unroll
        for (int off = 16; off; off >>= 1) {
            unsigned long long o = __shfl_xor_sync(FULL, best, off);
            if (o > best) best = o;
        }
        if (lane == 0) s_anch[g] = (int)(~(unsigned)(best & 0xFFFFFFFFu));
    }
    __syncthreads();
    // dedup (last write wins) + set bitmaps + append forced entries
    if (tid < count) {
        int g = tid;
        int a = s_anch[g];
        bool skip = false;
        for (int g2 = g + 1; g2 < count; ++g2)
            if (s_anch[g2] == a) { skip = true; break; }
        if (!skip) {
            unsigned bit = 1u << (a & 31);
            atomicOr(&g_bm[b * POSBMW + (a >> 5)], bit);
            unsigned old = atomicOr(&g_posbm[b * POSBMW + (a >> 5)], bit);
            if (!((old >> (a & 31)) & 1)) atomicAdd(&s_fnew, 1);   // new positive
            int j = atomicAdd(&s_fcnt, 1);
            g_flist[b * 64 + j] = ((unsigned)b << 23) | ((unsigned)a << 6) | (unsigned)g;
        }
    }
    __syncthreads();
    if (tid == 0) {
        int rs = 0;
        #pragma unroll
        for (int k = 0; k < 8; ++k) rs += s_regsum[k];
        g_fcnt[b] = s_fcnt;
        g_pos_cnt[b] = rs + s_fnew;
    }
}

// ========== Stage B: k5 role (x < NB) || k4 role (x >= NB); fused finalize ==
__global__ void kB(const float* __restrict__ conf, const float* __restrict__ pred,
                   const float* __restrict__ gts, const float* __restrict__ anchors,
                   float* __restrict__ out) {
    __shared__ int hist[2048];
    __shared__ unsigned s_pref;
    __shared__ int s_rem, s_selbin, s_above;
    __shared__ double sred[32];
    int tid = threadIdx.x;
    int lane = tid & 31;

    if (blockIdx.x < NB) {
        // ---------------- k5: radix-select + top-K negative sum --------------
        int b = blockIdx.x;
        const float* base = g_mining + (size_t)b * NA;
        const unsigned* pbm = g_posbm + b * POSBMW;
        int pc = g_pos_cnt[b];
        int K = 3 * pc;
        if (K > NA - pc) K = NA - pc;
        if (K > 0) {
            if (tid == 0) { s_rem = K; s_pref = 0u; }
            __syncthreads();
            for (int pass = 0; pass < 3; ++pass) {
                for (int i = tid; i < 2048; i += blockDim.x) hist[i] = 0;
                __syncthreads();
                unsigned pref = s_pref;
                int nb = (pass == 2) ? 1024 : 2048;
                for (int i0 = tid; i0 < NA; i0 += 8192) {
                    unsigned u[8]; bool val[8];
                    #pragma unroll
                    for (int j = 0; j < 8; ++j) {
                        int i = i0 + j * 1024;
                        bool inb = (i < NA);
                        bool posb = inb && ((pbm[i >> 5] >> (i & 31)) & 1);
                        val[j] = inb && !posb;
                        u[j] = val[j] ? fmap(base[i]) : 0u;
                    }
                    #pragma unroll
                    for (int j = 0; j < 8; ++j) {
                        unsigned bin; bool ok = val[j];
                        if (pass == 0)      { bin = u[j] >> 21; }
                        else if (pass == 1) { ok = ok && ((u[j] >> 21) == pref);  bin = (u[j] >> 10) & 0x7FFu; }
                        else                { ok = ok && ((u[j] >> 10) == pref);  bin = u[j] & 0x3FFu; }
                        unsigned mm = __match_any_sync(FULL, ok ? bin : 0xFFFFFFFFu);
                        if (ok && lane == (__ffs(mm) - 1)) atomicAdd(&hist[bin], __popc(mm));
                    }
                }
                __syncthreads();
                if (tid < 32) {
                    int cs = nb >> 5;
                    int s = 0;
                    for (int k = 0; k < cs; k++) s += hist[lane * cs + k];
                    int inc = s;
                    #pragma unroll
                    for (int off = 1; off < 32; off <<= 1) {
                        int t = __shfl_down_sync(FULL, inc, off);
                        if (lane + off < 32) inc += t;
                    }
                    int exc = inc - s;
                    int remv = s_rem;
                    bool hit = (exc < remv) && (inc >= remv);
                    unsigned bal = __ballot_sync(FULL, hit);
                    int src = __ffs(bal) - 1;
                    if (lane == src) {
                        int cum = exc, selbin = lane * cs;
                        for (int bb = lane * cs + cs - 1; bb >= lane * cs; --bb) {
                            int h = hist[bb];
                            if (cum + h >= remv) { selbin = bb; break; }
                            cum += h;
                        }
                        s_selbin = selbin;
                        s_above = cum;
                    }
                }
                __syncthreads();
                if (tid == 0) {
                    s_rem -= s_above;
                    s_pref = (pass == 0) ? (unsigned)s_selbin
                                         : ((s_pref << ((pass == 2) ? 10 : 11)) | (unsigned)s_selbin);
                }
                __syncthreads();
            }
            unsigned ut = s_pref;
            double s = 0.0;
            for (int i0 = tid; i0 < NA; i0 += 8192) {
                #pragma unroll
                for (int j = 0; j < 8; ++j) {
                    int i = i0 + j * 1024;
                    if (i < NA && !((pbm[i >> 5] >> (i & 31)) & 1)) {
                        float vv = base[i];
                        if (fmap(vv) > ut) s += (double)vv;
                    }
                }
            }
            #pragma unroll
            for (int off = 16; off; off >>= 1) s += __shfl_xor_sync(FULL, s, off);
            if (lane == 0) sred[tid >> 5] = s;
            __syncthreads();
            if (tid < 32) {
                double vv = (lane < (int)(blockDim.x >> 5)) ? sred[lane] : 0.0;
                #pragma unroll
                for (int off = 16; off; off >>= 1) vv += __shfl_xor_sync(FULL, vv, off);
                if (tid == 0) {
                    float tv = funmap(ut);
                    if (isfinite(tv)) vv += (double)s_rem * (double)tv;  // ties
                    g_neg_sum[b] = vv;
                }
            }
        } else if (tid == 0) {
            g_neg_sum[b] = 0.0;
        }
    } else {
        // ---------------- k4: positive CE + SmoothL1 -------------------------
        float ce_acc = 0.f, loc_acc = 0.f;
        const int total = REG_TOT + NB * 64;
        for (int s = (blockIdx.x - NB) * 1024 + tid; s < total; s += K4B * 1024) {
            int b, a, g;
            if (s < REG_TOT) {
                int cnt = g_blkcnt[s >> 8];
                if ((s & 255) >= cnt) continue;
                unsigned e = g_plist[s];
                b = (e >> 23) & 15; a = (e >> 6) & 0x1FFFF; g = e & 63;
                if ((g_bm[b * POSBMW + (a >> 5)] >> (a & 31)) & 1) continue; // superseded
            } else {
                int t = s - REG_TOT;
                b = t >> 6;
                if ((t & 63) >= g_fcnt[b]) continue;
                unsigned e = g_flist[t];
                a = (e >> 6) & 0x1FFFF; g = e & 63;
            }
            size_t ia = (size_t)b * NA + a;
            const float* gp = gts + ((size_t)b * NG + g) * 5;
            int label = (int)gp[4];
            const float* cp = conf + ia * NC;
            ce_acc += g_mining[ia] + cp[0] - cp[label];     // lse - conf[label]
            float4 av = reinterpret_cast<const float4*>(anchors)[a];
            float acx = (av.x + av.z) * 0.5f, acy = (av.y + av.w) * 0.5f;
            float aw = av.z - av.x, ah = av.w - av.y;
            float mcx = (gp[0] + gp[2]) * 0.5f, mcy = (gp[1] + gp[3]) * 0.5f;
            float mw = gp[2] - gp[0], mh = gp[3] - gp[1];
            float t0 = (mcx - acx) / (aw * 0.1f);
            float t1 = (mcy - acy) / (ah * 0.1f);
            float t2 = logf(mw / aw + 1e-10f) / 0.2f;
            float t3 = logf(mh / ah + 1e-10f) / 0.2f;
            float4 pv = reinterpret_cast<const float4*>(pred)[ia];
            const float BETA = (float)(1.0 / 9.0);
            float d;
            d = fabsf(pv.x - t0); loc_acc += (d < BETA) ? 0.5f * d * d / BETA : d - 0.5f * BETA;
            d = fabsf(pv.y - t1); loc_acc += (d < BETA) ? 0.5f * d * d / BETA : d - 0.5f * BETA;
            d = fabsf(pv.z - t2); loc_acc += (d < BETA) ? 0.5f * d * d / BETA : d - 0.5f * BETA;
            d = fabsf(pv.w - t3); loc_acc += (d < BETA) ? 0.5f * d * d / BETA : d - 0.5f * BETA;
        }
        // block reduction -> one pair of double atomics per block
        #pragma unroll
        for (int off = 16; off; off >>= 1) {
            ce_acc  += __shfl_xor_sync(FULL, ce_acc, off);
            loc_acc += __shfl_xor_sync(FULL, loc_acc, off);
        }
        __syncthreads();   // reuse sred safely
        if (lane == 0) { sred[tid >> 5] = (double)ce_acc; }
        __syncthreads();
        double ced = (tid < 32 && lane < 32) ? ((lane < 32) ? sred[lane] : 0.0) : 0.0;
        if (tid < 32) {
            #pragma unroll
            for (int off = 16; off; off >>= 1) ced += __shfl_xor_sync(FULL, ced, off);
        }
        __syncthreads();
        if (lane == 0) { sred[tid >> 5] = (double)loc_acc; }
        __syncthreads();
        if (tid < 32) {
            double lod = sred[lane];
            #pragma unroll
            for (int off = 16; off; off >>= 1) lod += __shfl_xor_sync(FULL, lod, off);
            if (tid == 0) {
                if (ced != 0.0) atomicAdd(&g_pos_ce, ced);
                if (lod != 0.0) atomicAdd(&g_loc_sum, lod);
            }
        }
    }
    // -------- fused finalize: last of all BTOT blocks writes outputs --------
    __syncthreads();
    if (tid == 0) {
        __threadfence();
        int d = atomicAdd(&g_done, 1);
        if (d == BTOT - 1) {
            __threadfence();
            int np = 0; double ns = 0.0;
            for (int bb = 0; bb < NB; bb++) { np += g_pos_cnt[bb]; ns += g_neg_sum[bb]; }
            float npf = fmaxf(1.f, (float)np);
            double denom = (double)npf * 4.0;
            out[0] = (float)(g_loc_sum / denom);          // localisation_loss
            out[1] = (float)((g_pos_ce + ns) / denom);    // classification_loss
            // reset accumulators for next (deterministic) run
            g_pos_ce = 0.0; g_loc_sum = 0.0; g_done = 0;
        }
    }
}

extern "C" void kernel_launch(void* const* d_in, const int* in_sizes, int n_in,
                              void* d_out, int out_size) {
    const float* conf    = (const float*)d_in[0];
    const float* pred    = (const float*)d_in[1];
    const float* gts     = (const float*)d_in[2];
    const int*   counts  = (const int*)d_in[3];
    const float* anchors = (const float*)d_in[4];
    float* out = (float*)d_out;

    kA<<<dim3(NBLK + NA / 16, NB), 256>>>(conf, gts, counts, anchors);
    kRS<<<NB, 512>>>(counts);
    kB<<<BTOT, 1024>>>(conf, pred, gts, anchors, out);
}